// round 2
// baseline (speedup 1.0000x reference)
#include <cuda_runtime.h>
#include <cuda_bf16.h>
#include <cstdint>

#define DI __device__ __forceinline__

static constexpr int BROWS = 16384;
static constexpr int DDIM  = 256;
static constexpr int C1    = 1024;
static constexpr int C2    = 512;
static constexpr int NPR   = C1 + C2;

// scratch: normalized bf16 images then prompts (color rows, then shape rows)
__device__ __nv_bfloat16 g_z[(BROWS + NPR) * DDIM];
__device__ float g_rowExp[2 * BROWS];
__device__ float g_rowSim[2 * BROWS];
__device__ float g_rowNp [2 * BROWS];

// ---------------- helpers ----------------
DI uint32_t smem_u32(const void* p) {
    uint32_t a;
    asm("{ .reg .u64 t; cvta.to.shared.u64 t, %1; cvt.u32.u64 %0, t; }" : "=r"(a) : "l"(p));
    return a;
}
DI void cp16(uint32_t dst, const void* src) {
    asm volatile("cp.async.cg.shared.global [%0], [%1], 16;" :: "r"(dst), "l"(src));
}
DI void cp_commit() { asm volatile("cp.async.commit_group;"); }
template <int N> DI void cp_wait() {
    asm volatile("cp.async.wait_group %0;" :: "n"(N) : "memory");
}
DI void ldmatrix_x4(uint32_t& r0, uint32_t& r1, uint32_t& r2, uint32_t& r3, uint32_t addr) {
    asm volatile("ldmatrix.sync.aligned.m8n8.x4.shared.b16 {%0,%1,%2,%3}, [%4];"
                 : "=r"(r0), "=r"(r1), "=r"(r2), "=r"(r3) : "r"(addr));
}
DI void mma_bf16(float& d0, float& d1, float& d2, float& d3,
                 uint32_t a0, uint32_t a1, uint32_t a2, uint32_t a3,
                 uint32_t b0, uint32_t b1) {
    asm volatile("mma.sync.aligned.m16n8k16.row.col.f32.bf16.bf16.f32 "
                 "{%0,%1,%2,%3}, {%4,%5,%6,%7}, {%8,%9}, {%0,%1,%2,%3};"
                 : "+f"(d0), "+f"(d1), "+f"(d2), "+f"(d3)
                 : "r"(a0), "r"(a1), "r"(a2), "r"(a3), "r"(b0), "r"(b1));
}

// ---------------- SMEM layout ----------------
// [0,1536)      : per-row accumulators sE/sX/sN (3 x 128 floats)
// [2048,67584)  : A tile, 4 chunks of 128x64 bf16 (16 KB each, swizzled 128B rows)
// [67584,133120): B tile, same
// [133120,...)  : labels 128 rows x 132 ints (pad 4)
static constexpr int A_OFF = 2048;
static constexpr int B_OFF = A_OFF + 4 * 16384;
static constexpr int L_OFF = B_OFF + 4 * 16384;
static constexpr int LAB_STRIDE = 132;
static constexpr int SMEM_BYTES = L_OFF + 128 * LAB_STRIDE * 4;   // 200704

// ---------------- kernels ----------------
__global__ void zero_kernel() {
    int i = blockIdx.x * blockDim.x + threadIdx.x;
    if (i < 2 * BROWS) { g_rowExp[i] = 0.f; g_rowSim[i] = 0.f; g_rowNp[i] = 0.f; }
}

// one warp per row: L2-normalize (clamp 1e-12) and convert to bf16
__global__ void norm_kernel(const float* __restrict__ img,
                            const float* __restrict__ pc,
                            const float* __restrict__ ps) {
    int warp = (blockIdx.x * blockDim.x + threadIdx.x) >> 5;
    int lane = threadIdx.x & 31;
    if (warp >= BROWS + NPR) return;
    const float* src;
    if (warp < BROWS)            src = img + (size_t)warp * DDIM;
    else if (warp < BROWS + C1)  src = pc  + (size_t)(warp - BROWS) * DDIM;
    else                         src = ps  + (size_t)(warp - BROWS - C1) * DDIM;

    float4 v0 = ((const float4*)src)[lane];
    float4 v1 = ((const float4*)src)[lane + 32];
    float ss = v0.x*v0.x + v0.y*v0.y + v0.z*v0.z + v0.w*v0.w
             + v1.x*v1.x + v1.y*v1.y + v1.z*v1.z + v1.w*v1.w;
    #pragma unroll
    for (int o = 16; o; o >>= 1) ss += __shfl_xor_sync(0xFFFFFFFFu, ss, o);
    float r = 1.f / fmaxf(sqrtf(ss), 1e-12f);

    __nv_bfloat162* d2 = (__nv_bfloat162*)(g_z + (size_t)warp * DDIM);
    d2[lane * 2 + 0]        = __floats2bfloat162_rn(v0.x * r, v0.y * r);
    d2[lane * 2 + 1]        = __floats2bfloat162_rn(v0.z * r, v0.w * r);
    d2[(lane + 32) * 2 + 0] = __floats2bfloat162_rn(v1.x * r, v1.y * r);
    d2[(lane + 32) * 2 + 1] = __floats2bfloat162_rn(v1.z * r, v1.w * r);
}

// load one 128x64 bf16 chunk into swizzled SMEM (128B rows, 16B-unit xor swizzle)
DI void load_chunk(uint32_t sbase, const char* g, int tid) {
    #pragma unroll
    for (int j = 0; j < 4; j++) {
        int i = tid + j * 256;            // 1024 16B units
        int row = i >> 3, u = i & 7;
        uint32_t dst = sbase + row * 128 + ((u ^ (row & 7)) << 4);
        cp16(dst, g + (size_t)row * 512 + u * 16);
    }
}

// fused 128x128xK256 bf16 mma.sync GEMM + masked softmax-partial epilogue
__global__ void __launch_bounds__(256, 1)
gemm_kernel(const int* __restrict__ labels_color, const int* __restrict__ labels_shape) {
    extern __shared__ char smem_c[];
    uint32_t sb = smem_u32(smem_c);
    int tid = threadIdx.x, wid = tid >> 5, lane = tid & 31;

    int bx   = blockIdx.x;
    int attr = (bx >= 8) ? 1 : 0;
    int nt   = attr ? (bx - 8) : bx;
    int Cdim = attr ? C2 : C1;
    const int* labels = attr ? labels_shape : labels_color;
    int m0 = blockIdx.y * 128;
    int n0 = nt * 128;
    const char* Ag = (const char*)(g_z + (size_t)m0 * DDIM);
    const char* Bg = (const char*)(g_z + (size_t)(BROWS + (attr ? C1 : 0) + n0) * DDIM);

    float* sE = (float*)smem_c;
    float* sX = sE + 128;
    float* sN = sE + 256;
    if (tid < 128) { sE[tid] = 0.f; sX[tid] = 0.f; sN[tid] = 0.f; }

    // issue all async copies: chunk groups g0..g3, labels g4
    #pragma unroll
    for (int c = 0; c < 4; c++) {
        load_chunk(sb + A_OFF + c * 16384, Ag + c * 128, tid);
        load_chunk(sb + B_OFF + c * 16384, Bg + c * 128, tid);
        cp_commit();
    }
    #pragma unroll
    for (int j = 0; j < 16; j++) {
        int i = tid + j * 256;            // 4096 16B units
        int row = i >> 5, u = i & 31;
        cp16(sb + L_OFF + (uint32_t)(row * (LAB_STRIDE * 4) + u * 16),
             labels + (size_t)(m0 + row) * Cdim + n0 + u * 4);
    }
    cp_commit();

    // warp layout: 2 (M) x 4 (N); warp tile 64x32
    int wm = wid & 1, wn = wid >> 1;
    float acc[4][4][4];
    #pragma unroll
    for (int i = 0; i < 4; i++)
        #pragma unroll
        for (int j = 0; j < 4; j++)
            #pragma unroll
            for (int k = 0; k < 4; k++) acc[i][j][k] = 0.f;

    int l15 = lane & 15, sw = lane & 7, hi = lane >> 4;

    #pragma unroll
    for (int c = 0; c < 4; c++) {
        if      (c == 0) cp_wait<4>();
        else if (c == 1) cp_wait<3>();
        else if (c == 2) cp_wait<2>();
        else             cp_wait<1>();
        __syncthreads();
        uint32_t abase = sb + A_OFF + c * 16384;
        uint32_t bbase = sb + B_OFF + c * 16384;
        #pragma unroll
        for (int k = 0; k < 4; k++) {
            uint32_t uoff = (uint32_t)(((k * 2 + hi) ^ sw) << 4);
            uint32_t a[4][4], b[2][4];
            #pragma unroll
            for (int mi = 0; mi < 4; mi++)
                ldmatrix_x4(a[mi][0], a[mi][1], a[mi][2], a[mi][3],
                            abase + (uint32_t)((wm * 64 + mi * 16 + l15) * 128) + uoff);
            #pragma unroll
            for (int nj = 0; nj < 2; nj++)
                ldmatrix_x4(b[nj][0], b[nj][1], b[nj][2], b[nj][3],
                            bbase + (uint32_t)((wn * 32 + nj * 16 + l15) * 128) + uoff);
            #pragma unroll
            for (int mi = 0; mi < 4; mi++)
                #pragma unroll
                for (int nj = 0; nj < 4; nj++)
                    mma_bf16(acc[mi][nj][0], acc[mi][nj][1], acc[mi][nj][2], acc[mi][nj][3],
                             a[mi][0], a[mi][1], a[mi][2], a[mi][3],
                             b[nj >> 1][nj & 1], b[nj >> 1][2 + (nj & 1)]);
        }
    }

    cp_wait<0>();
    __syncthreads();

    // epilogue: per-row masked sum of exp(10*acc), 10*acc, count
    const int* labi = (const int*)(smem_c + L_OFF);
    int q = lane >> 2, r4 = lane & 3;
    #pragma unroll
    for (int mi = 0; mi < 4; mi++) {
        #pragma unroll
        for (int h = 0; h < 2; h++) {
            int row = wm * 64 + mi * 16 + q + h * 8;
            float se = 0.f, sx = 0.f, np = 0.f;
            #pragma unroll
            for (int nj = 0; nj < 4; nj++) {
                int col = wn * 32 + nj * 8 + 2 * r4;
                int2 lb = *(const int2*)(labi + row * LAB_STRIDE + col);
                float s0 = acc[mi][nj][2 * h + 0] * 10.f;
                float s1 = acc[mi][nj][2 * h + 1] * 10.f;
                if (lb.x > 0) { se += __expf(s0); sx += s0; np += 1.f; }
                if (lb.y > 0) { se += __expf(s1); sx += s1; np += 1.f; }
            }
            se += __shfl_xor_sync(0xFFFFFFFFu, se, 1);
            se += __shfl_xor_sync(0xFFFFFFFFu, se, 2);
            sx += __shfl_xor_sync(0xFFFFFFFFu, sx, 1);
            sx += __shfl_xor_sync(0xFFFFFFFFu, sx, 2);
            np += __shfl_xor_sync(0xFFFFFFFFu, np, 1);
            np += __shfl_xor_sync(0xFFFFFFFFu, np, 2);
            if (r4 == 0) {
                atomicAdd(&sE[row], se);
                atomicAdd(&sX[row], sx);
                atomicAdd(&sN[row], np);
            }
        }
    }
    __syncthreads();
    if (tid < 128) {
        int gr = attr * BROWS + m0 + tid;
        atomicAdd(&g_rowExp[gr], sE[tid]);
        atomicAdd(&g_rowSim[gr], sX[tid]);
        atomicAdd(&g_rowNp[gr],  sN[tid]);
    }
}

__global__ void final_kernel(float* out) {
    __shared__ float sh[4][256];
    int t = threadIdx.x;
    float v0 = 0.f, c0 = 0.f, v1 = 0.f, c1 = 0.f;
    for (int i = t; i < BROWS; i += 256) {
        float np = g_rowNp[i];
        if (np > 0.f) {
            float S = g_rowExp[i] + (1024.f - np);
            v0 += (np * logf(S) - g_rowSim[i]) / (np + 1e-8f);
            c0 += 1.f;
        }
        np = g_rowNp[BROWS + i];
        if (np > 0.f) {
            float S = g_rowExp[BROWS + i] + (512.f - np);
            v1 += (np * logf(S) - g_rowSim[BROWS + i]) / (np + 1e-8f);
            c1 += 1.f;
        }
    }
    sh[0][t] = v0; sh[1][t] = c0; sh[2][t] = v1; sh[3][t] = c1;
    __syncthreads();
    for (int s = 128; s; s >>= 1) {
        if (t < s) {
            sh[0][t] += sh[0][t + s]; sh[1][t] += sh[1][t + s];
            sh[2][t] += sh[2][t + s]; sh[3][t] += sh[3][t + s];
        }
        __syncthreads();
    }
    if (t == 0) {
        float l1 = sh[0][0] / fmaxf(sh[1][0], 1.f);
        float l2 = sh[2][0] / fmaxf(sh[3][0], 1.f);
        float n1 = (sh[1][0] > 0.f) ? 1.f : 0.f;
        float n2 = (sh[3][0] > 0.f) ? 1.f : 0.f;
        float nv = n1 + n2;
        out[0] = (nv > 0.f) ? (l1 * n1 + l2 * n2) / fmaxf(nv, 1.f) : 0.f;
    }
}

extern "C" void kernel_launch(void* const* d_in, const int* in_sizes, int n_in,
                              void* d_out, int out_size) {
    const float* img = (const float*)d_in[0];
    const float* pc  = (const float*)d_in[1];
    const float* ps  = (const float*)d_in[2];
    const int*   lc  = (const int*)d_in[3];
    const int*   lsh = (const int*)d_in[4];

    zero_kernel<<<(2 * BROWS + 255) / 256, 256>>>();
    norm_kernel<<<((BROWS + NPR) * 32 + 255) / 256, 256>>>(img, pc, ps);

    cudaFuncSetAttribute(gemm_kernel, cudaFuncAttributeMaxDynamicSharedMemorySize, SMEM_BYTES);
    gemm_kernel<<<dim3(12, 128), 256, SMEM_BYTES>>>(lc, lsh);

    final_kernel<<<1, 256>>>((float*)d_out);
}

// round 4
// speedup vs baseline: 1.7403x; 1.7403x over previous
#include <cuda_runtime.h>
#include <cuda_bf16.h>
#include <cstdint>

#define DI __device__ __forceinline__

static constexpr int BROWS = 16384;
static constexpr int DDIM  = 256;
static constexpr int C1    = 1024;
static constexpr int C2    = 512;
static constexpr int NPR   = C1 + C2;

// scratch: normalized bf16 images then prompts (color rows, then shape rows)
__device__ __nv_bfloat16 g_z[(BROWS + NPR) * DDIM];
__device__ float g_rowExp[2 * BROWS];
__device__ float g_rowSim[2 * BROWS];
__device__ float g_rowNp [2 * BROWS];
__device__ float g_acc[4];   // v0, c0, v1, c1

// ---------------- helpers ----------------
DI uint32_t smem_u32(const void* p) {
    uint32_t a;
    asm("{ .reg .u64 t; cvta.to.shared.u64 t, %1; cvt.u32.u64 %0, t; }" : "=r"(a) : "l"(p));
    return a;
}
DI void cp16(uint32_t dst, const void* src) {
    asm volatile("cp.async.cg.shared.global [%0], [%1], 16;" :: "r"(dst), "l"(src));
}
DI void cp_commit() { asm volatile("cp.async.commit_group;"); }
template <int N> DI void cp_wait() {
    asm volatile("cp.async.wait_group %0;" :: "n"(N) : "memory");
}
DI void ldmatrix_x4(uint32_t& r0, uint32_t& r1, uint32_t& r2, uint32_t& r3, uint32_t addr) {
    asm volatile("ldmatrix.sync.aligned.m8n8.x4.shared.b16 {%0,%1,%2,%3}, [%4];"
                 : "=r"(r0), "=r"(r1), "=r"(r2), "=r"(r3) : "r"(addr));
}
DI void mma_bf16(float& d0, float& d1, float& d2, float& d3,
                 uint32_t a0, uint32_t a1, uint32_t a2, uint32_t a3,
                 uint32_t b0, uint32_t b1) {
    asm volatile("mma.sync.aligned.m16n8k16.row.col.f32.bf16.bf16.f32 "
                 "{%0,%1,%2,%3}, {%4,%5,%6,%7}, {%8,%9}, {%0,%1,%2,%3};"
                 : "+f"(d0), "+f"(d1), "+f"(d2), "+f"(d3)
                 : "r"(a0), "r"(a1), "r"(a2), "r"(a3), "r"(b0), "r"(b1));
}

// ---------------- SMEM layout ----------------
static constexpr int A_OFF = 2048;
static constexpr int B_OFF = A_OFF + 4 * 16384;
static constexpr int L_OFF = B_OFF + 4 * 16384;
static constexpr int LAB_STRIDE = 132;
static constexpr int SMEM_BYTES = L_OFF + 128 * LAB_STRIDE * 4;   // 200704

// ---------------- kernels ----------------
__global__ void zero_kernel() {
    int i = blockIdx.x * blockDim.x + threadIdx.x;
    if (i < 2 * BROWS) { g_rowExp[i] = 0.f; g_rowSim[i] = 0.f; g_rowNp[i] = 0.f; }
    if (i < 4) g_acc[i] = 0.f;
}

// one warp per row: L2-normalize (clamp 1e-12) and convert to bf16
__global__ void norm_kernel(const float* __restrict__ img,
                            const float* __restrict__ pc,
                            const float* __restrict__ ps) {
    int warp = (blockIdx.x * blockDim.x + threadIdx.x) >> 5;
    int lane = threadIdx.x & 31;
    if (warp >= BROWS + NPR) return;
    const float* src;
    if (warp < BROWS)            src = img + (size_t)warp * DDIM;
    else if (warp < BROWS + C1)  src = pc  + (size_t)(warp - BROWS) * DDIM;
    else                         src = ps  + (size_t)(warp - BROWS - C1) * DDIM;

    float4 v0 = ((const float4*)src)[lane];
    float4 v1 = ((const float4*)src)[lane + 32];
    float ss = v0.x*v0.x + v0.y*v0.y + v0.z*v0.z + v0.w*v0.w
             + v1.x*v1.x + v1.y*v1.y + v1.z*v1.z + v1.w*v1.w;
    #pragma unroll
    for (int o = 16; o; o >>= 1) ss += __shfl_xor_sync(0xFFFFFFFFu, ss, o);
    float r = 1.f / fmaxf(sqrtf(ss), 1e-12f);

    __nv_bfloat162* d2 = (__nv_bfloat162*)(g_z + (size_t)warp * DDIM);
    d2[lane * 2 + 0]        = __floats2bfloat162_rn(v0.x * r, v0.y * r);
    d2[lane * 2 + 1]        = __floats2bfloat162_rn(v0.z * r, v0.w * r);
    d2[(lane + 32) * 2 + 0] = __floats2bfloat162_rn(v1.x * r, v1.y * r);
    d2[(lane + 32) * 2 + 1] = __floats2bfloat162_rn(v1.z * r, v1.w * r);
}

// load one 128x64 bf16 chunk into swizzled SMEM (128B rows, 16B-unit xor swizzle)
DI void load_chunk(uint32_t sbase, const char* g, int tid) {
    #pragma unroll
    for (int j = 0; j < 4; j++) {
        int i = tid + j * 256;            // 1024 16B units
        int row = i >> 3, u = i & 7;
        uint32_t dst = sbase + row * 128 + ((u ^ (row & 7)) << 4);
        cp16(dst, g + (size_t)row * 512 + u * 16);
    }
}

// fused 128x128xK256 bf16 mma.sync GEMM + masked softmax-partial epilogue
__global__ void __launch_bounds__(256, 1)
gemm_kernel(const int* __restrict__ labels_color, const int* __restrict__ labels_shape) {
    extern __shared__ char smem_c[];
    uint32_t sb = smem_u32(smem_c);
    int tid = threadIdx.x, wid = tid >> 5, lane = tid & 31;

    int bx   = blockIdx.x;
    int attr = (bx >= 8) ? 1 : 0;
    int nt   = attr ? (bx - 8) : bx;
    int Cdim = attr ? C2 : C1;
    const int* labels = attr ? labels_shape : labels_color;
    int m0 = blockIdx.y * 128;
    int n0 = nt * 128;
    const char* Ag = (const char*)(g_z + (size_t)m0 * DDIM);
    const char* Bg = (const char*)(g_z + (size_t)(BROWS + (attr ? C1 : 0) + n0) * DDIM);

    float* sE = (float*)smem_c;
    float* sX = sE + 128;
    float* sN = sE + 256;
    if (tid < 128) { sE[tid] = 0.f; sX[tid] = 0.f; sN[tid] = 0.f; }

    // issue all async copies: chunk groups g0..g3, labels g4
    #pragma unroll
    for (int c = 0; c < 4; c++) {
        load_chunk(sb + A_OFF + c * 16384, Ag + c * 128, tid);
        load_chunk(sb + B_OFF + c * 16384, Bg + c * 128, tid);
        cp_commit();
    }
    #pragma unroll
    for (int j = 0; j < 16; j++) {
        int i = tid + j * 256;            // 4096 16B units
        int row = i >> 5, u = i & 31;
        cp16(sb + L_OFF + (uint32_t)(row * (LAB_STRIDE * 4) + u * 16),
             labels + (size_t)(m0 + row) * Cdim + n0 + u * 4);
    }
    cp_commit();

    // warp layout: 2 (M) x 4 (N); warp tile 64x32
    int wm = wid & 1, wn = wid >> 1;
    float acc[4][4][4];
    #pragma unroll
    for (int i = 0; i < 4; i++)
        #pragma unroll
        for (int j = 0; j < 4; j++)
            #pragma unroll
            for (int k = 0; k < 4; k++) acc[i][j][k] = 0.f;

    int l15 = lane & 15, sw = lane & 7, hi = lane >> 4;

    #pragma unroll
    for (int c = 0; c < 4; c++) {
        if      (c == 0) cp_wait<4>();
        else if (c == 1) cp_wait<3>();
        else if (c == 2) cp_wait<2>();
        else             cp_wait<1>();
        __syncthreads();
        uint32_t abase = sb + A_OFF + c * 16384;
        uint32_t bbase = sb + B_OFF + c * 16384;
        #pragma unroll
        for (int k = 0; k < 4; k++) {
            uint32_t uoff = (uint32_t)(((k * 2 + hi) ^ sw) << 4);
            uint32_t a[4][4], b[2][4];
            #pragma unroll
            for (int mi = 0; mi < 4; mi++)
                ldmatrix_x4(a[mi][0], a[mi][1], a[mi][2], a[mi][3],
                            abase + (uint32_t)((wm * 64 + mi * 16 + l15) * 128) + uoff);
            #pragma unroll
            for (int nj = 0; nj < 2; nj++)
                ldmatrix_x4(b[nj][0], b[nj][1], b[nj][2], b[nj][3],
                            bbase + (uint32_t)((wn * 32 + nj * 16 + l15) * 128) + uoff);
            #pragma unroll
            for (int mi = 0; mi < 4; mi++)
                #pragma unroll
                for (int nj = 0; nj < 4; nj++)
                    mma_bf16(acc[mi][nj][0], acc[mi][nj][1], acc[mi][nj][2], acc[mi][nj][3],
                             a[mi][0], a[mi][1], a[mi][2], a[mi][3],
                             b[nj >> 1][nj & 1], b[nj >> 1][2 + (nj & 1)]);
        }
    }

    cp_wait<0>();
    __syncthreads();

    // epilogue: per-row masked sum of exp(10*acc), 10*acc, count
    const int* labi = (const int*)(smem_c + L_OFF);
    int q = lane >> 2, r4 = lane & 3;
    #pragma unroll
    for (int mi = 0; mi < 4; mi++) {
        #pragma unroll
        for (int h = 0; h < 2; h++) {
            int row = wm * 64 + mi * 16 + q + h * 8;
            float se = 0.f, sx = 0.f, np = 0.f;
            #pragma unroll
            for (int nj = 0; nj < 4; nj++) {
                int col = wn * 32 + nj * 8 + 2 * r4;
                int2 lb = *(const int2*)(labi + row * LAB_STRIDE + col);
                float s0 = acc[mi][nj][2 * h + 0] * 10.f;
                float s1 = acc[mi][nj][2 * h + 1] * 10.f;
                if (lb.x > 0) { se += __expf(s0); sx += s0; np += 1.f; }
                if (lb.y > 0) { se += __expf(s1); sx += s1; np += 1.f; }
            }
            se += __shfl_xor_sync(0xFFFFFFFFu, se, 1);
            se += __shfl_xor_sync(0xFFFFFFFFu, se, 2);
            sx += __shfl_xor_sync(0xFFFFFFFFu, sx, 1);
            sx += __shfl_xor_sync(0xFFFFFFFFu, sx, 2);
            np += __shfl_xor_sync(0xFFFFFFFFu, np, 1);
            np += __shfl_xor_sync(0xFFFFFFFFu, np, 2);
            if (r4 == 0) {
                atomicAdd(&sE[row], se);
                atomicAdd(&sX[row], sx);
                atomicAdd(&sN[row], np);
            }
        }
    }
    __syncthreads();
    if (tid < 128) {
        int gr = attr * BROWS + m0 + tid;
        atomicAdd(&g_rowExp[gr], sE[tid]);
        atomicAdd(&g_rowSim[gr], sX[tid]);
        atomicAdd(&g_rowNp[gr],  sN[tid]);
    }
}

// parallel finalize: 64 blocks reduce per-row losses into g_acc[4]
__global__ void reduce_kernel() {
    __shared__ float sh[4][256];
    int t = threadIdx.x;
    int gstride = gridDim.x * blockDim.x;
    float v0 = 0.f, c0 = 0.f, v1 = 0.f, c1 = 0.f;
    for (int i = blockIdx.x * blockDim.x + t; i < BROWS; i += gstride) {
        float np = g_rowNp[i];
        if (np > 0.f) {
            float S = g_rowExp[i] + (1024.f - np);
            v0 += (np * logf(S) - g_rowSim[i]) / (np + 1e-8f);
            c0 += 1.f;
        }
        np = g_rowNp[BROWS + i];
        if (np > 0.f) {
            float S = g_rowExp[BROWS + i] + (512.f - np);
            v1 += (np * logf(S) - g_rowSim[BROWS + i]) / (np + 1e-8f);
            c1 += 1.f;
        }
    }
    sh[0][t] = v0; sh[1][t] = c0; sh[2][t] = v1; sh[3][t] = c1;
    __syncthreads();
    #pragma unroll
    for (int s = 128; s; s >>= 1) {
        if (t < s) {
            sh[0][t] += sh[0][t + s]; sh[1][t] += sh[1][t + s];
            sh[2][t] += sh[2][t + s]; sh[3][t] += sh[3][t + s];
        }
        __syncthreads();
    }
    if (t < 4) atomicAdd(&g_acc[t], sh[t][0]);
}

__global__ void scalar_kernel(float* out) {
    float sv0 = g_acc[0], sc0 = g_acc[1], sv1 = g_acc[2], sc1 = g_acc[3];
    float l1 = sv0 / fmaxf(sc0, 1.f);
    float l2 = sv1 / fmaxf(sc1, 1.f);
    float n1 = (sc0 > 0.f) ? 1.f : 0.f;
    float n2 = (sc1 > 0.f) ? 1.f : 0.f;
    float nv = n1 + n2;
    out[0] = (nv > 0.f) ? (l1 * n1 + l2 * n2) / fmaxf(nv, 1.f) : 0.f;
}

extern "C" void kernel_launch(void* const* d_in, const int* in_sizes, int n_in,
                              void* d_out, int out_size) {
    const float* img = (const float*)d_in[0];
    const float* pc  = (const float*)d_in[1];
    const float* ps  = (const float*)d_in[2];
    const int*   lc  = (const int*)d_in[3];
    const int*   lsh = (const int*)d_in[4];

    zero_kernel<<<(2 * BROWS + 255) / 256, 256>>>();
    norm_kernel<<<((BROWS + NPR) * 32 + 255) / 256, 256>>>(img, pc, ps);

    cudaFuncSetAttribute(gemm_kernel, cudaFuncAttributeMaxDynamicSharedMemorySize, SMEM_BYTES);
    gemm_kernel<<<dim3(12, 128), 256, SMEM_BYTES>>>(lc, lsh);

    reduce_kernel<<<64, 256>>>();
    scalar_kernel<<<1, 1>>>((float*)d_out);
}

// round 5
// speedup vs baseline: 2.0853x; 1.1983x over previous
#include <cuda_runtime.h>
#include <cuda_bf16.h>
#include <cstdint>

#define DI __device__ __forceinline__

static constexpr int BROWS = 16384;
static constexpr int DDIM  = 256;
static constexpr int C1    = 1024;
static constexpr int C2    = 512;
static constexpr int NPR   = C1 + C2;

// scratch: normalized bf16 images then prompts (color rows, then shape rows)
__device__ __nv_bfloat16 g_z[(BROWS + NPR) * DDIM];
__device__ float g_rowExp[2 * BROWS];
__device__ float g_rowSim[2 * BROWS];
__device__ float g_rowNp [2 * BROWS];
__device__ float g_acc[4];   // v0, c0, v1, c1

// ---------------- helpers ----------------
DI uint32_t smem_u32(const void* p) {
    uint32_t a;
    asm("{ .reg .u64 t; cvta.to.shared.u64 t, %1; cvt.u32.u64 %0, t; }" : "=r"(a) : "l"(p));
    return a;
}
DI void cp16(uint32_t dst, const void* src) {
    asm volatile("cp.async.cg.shared.global [%0], [%1], 16;" :: "r"(dst), "l"(src));
}
DI void cp_commit() { asm volatile("cp.async.commit_group;"); }
template <int N> DI void cp_wait() {
    asm volatile("cp.async.wait_group %0;" :: "n"(N) : "memory");
}
DI void ldmatrix_x4(uint32_t& r0, uint32_t& r1, uint32_t& r2, uint32_t& r3, uint32_t addr) {
    asm volatile("ldmatrix.sync.aligned.m8n8.x4.shared.b16 {%0,%1,%2,%3}, [%4];"
                 : "=r"(r0), "=r"(r1), "=r"(r2), "=r"(r3) : "r"(addr));
}
DI void mma_bf16(float& d0, float& d1, float& d2, float& d3,
                 uint32_t a0, uint32_t a1, uint32_t a2, uint32_t a3,
                 uint32_t b0, uint32_t b1) {
    asm volatile("mma.sync.aligned.m16n8k16.row.col.f32.bf16.bf16.f32 "
                 "{%0,%1,%2,%3}, {%4,%5,%6,%7}, {%8,%9}, {%0,%1,%2,%3};"
                 : "+f"(d0), "+f"(d1), "+f"(d2), "+f"(d3)
                 : "r"(a0), "r"(a1), "r"(a2), "r"(a3), "r"(b0), "r"(b1));
}

// ---------------- SMEM layout ----------------
// [0,1536)   : per-row accumulators sE/sX/sN
// [2048,...) : 3 pipeline stages, each A-chunk(16 KB) + B-chunk(16 KB)
static constexpr int STG_OFF   = 2048;
static constexpr int STG_BYTES = 32768;
static constexpr int SMEM_BYTES = STG_OFF + 3 * STG_BYTES;   // 100352 -> 2 CTAs/SM

// ---------------- kernels ----------------
__global__ void zero_kernel() {
    int i = blockIdx.x * blockDim.x + threadIdx.x;
    if (i < 2 * BROWS) { g_rowExp[i] = 0.f; g_rowSim[i] = 0.f; g_rowNp[i] = 0.f; }
    if (i < 4) g_acc[i] = 0.f;
}

// one warp per row: L2-normalize (clamp 1e-12) and convert to bf16
__global__ void norm_kernel(const float* __restrict__ img,
                            const float* __restrict__ pc,
                            const float* __restrict__ ps) {
    int warp = (blockIdx.x * blockDim.x + threadIdx.x) >> 5;
    int lane = threadIdx.x & 31;
    if (warp >= BROWS + NPR) return;
    const float* src;
    if (warp < BROWS)            src = img + (size_t)warp * DDIM;
    else if (warp < BROWS + C1)  src = pc  + (size_t)(warp - BROWS) * DDIM;
    else                         src = ps  + (size_t)(warp - BROWS - C1) * DDIM;

    float4 v0 = ((const float4*)src)[lane];
    float4 v1 = ((const float4*)src)[lane + 32];
    float ss = v0.x*v0.x + v0.y*v0.y + v0.z*v0.z + v0.w*v0.w
             + v1.x*v1.x + v1.y*v1.y + v1.z*v1.z + v1.w*v1.w;
    #pragma unroll
    for (int o = 16; o; o >>= 1) ss += __shfl_xor_sync(0xFFFFFFFFu, ss, o);
    float r = 1.f / fmaxf(sqrtf(ss), 1e-12f);

    __nv_bfloat162* d2 = (__nv_bfloat162*)(g_z + (size_t)warp * DDIM);
    d2[lane * 2 + 0]        = __floats2bfloat162_rn(v0.x * r, v0.y * r);
    d2[lane * 2 + 1]        = __floats2bfloat162_rn(v0.z * r, v0.w * r);
    d2[(lane + 32) * 2 + 0] = __floats2bfloat162_rn(v1.x * r, v1.y * r);
    d2[(lane + 32) * 2 + 1] = __floats2bfloat162_rn(v1.z * r, v1.w * r);
}

// load one K-chunk (A 128x64 + B 128x64 bf16) into a pipeline stage
// swizzled 128B rows, 16B-unit xor swizzle
DI void load_stage(uint32_t sbase, const char* Ag, const char* Bg, int c, int tid) {
    const char* ga = Ag + c * 128;
    const char* gb = Bg + c * 128;
    #pragma unroll
    for (int j = 0; j < 4; j++) {
        int i = tid + j * 256;            // 1024 16B units per matrix
        int row = i >> 3, u = i & 7;
        uint32_t dst = sbase + row * 128 + ((u ^ (row & 7)) << 4);
        cp16(dst,         ga + (size_t)row * 512 + u * 16);
        cp16(dst + 16384, gb + (size_t)row * 512 + u * 16);
    }
}

// fused 128x128xK256 bf16 mma.sync GEMM + masked softmax-partial epilogue
__global__ void __launch_bounds__(256, 2)
gemm_kernel(const int* __restrict__ labels_color, const int* __restrict__ labels_shape) {
    extern __shared__ char smem_c[];
    uint32_t sb = smem_u32(smem_c);
    int tid = threadIdx.x, wid = tid >> 5, lane = tid & 31;

    int bx   = blockIdx.x;
    int attr = (bx >= 8) ? 1 : 0;
    int nt   = attr ? (bx - 8) : bx;
    int Cdim = attr ? C2 : C1;
    const int* labels = attr ? labels_shape : labels_color;
    int m0 = blockIdx.y * 128;
    int n0 = nt * 128;
    const char* Ag = (const char*)(g_z + (size_t)m0 * DDIM);
    const char* Bg = (const char*)(g_z + (size_t)(BROWS + (attr ? C1 : 0) + n0) * DDIM);

    float* sE = (float*)smem_c;
    float* sX = sE + 128;
    float* sN = sE + 256;
    if (tid < 128) { sE[tid] = 0.f; sX[tid] = 0.f; sN[tid] = 0.f; }

    // prologue: prefetch chunks 0,1 into stages 0,1
    load_stage(sb + STG_OFF, Ag, Bg, 0, tid); cp_commit();
    load_stage(sb + STG_OFF + STG_BYTES, Ag, Bg, 1, tid); cp_commit();

    // warp layout: 2 (M) x 4 (N); warp tile 64x32
    int wm = wid & 1, wn = wid >> 1;
    float acc[4][4][4];
    #pragma unroll
    for (int i = 0; i < 4; i++)
        #pragma unroll
        for (int j = 0; j < 4; j++)
            #pragma unroll
            for (int k = 0; k < 4; k++) acc[i][j][k] = 0.f;

    int l15 = lane & 15, sw = lane & 7, hi = lane >> 4;

    #pragma unroll
    for (int c = 0; c < 4; c++) {
        if (c + 2 < 4)
            load_stage(sb + STG_OFF + ((c + 2) % 3) * STG_BYTES, Ag, Bg, c + 2, tid);
        cp_commit();                 // uniform group count (may be empty)
        cp_wait<2>();                // chunk c landed
        __syncthreads();

        uint32_t abase = sb + STG_OFF + (c % 3) * STG_BYTES;
        uint32_t bbase = abase + 16384;
        #pragma unroll
        for (int k = 0; k < 4; k++) {
            uint32_t uoff = (uint32_t)(((k * 2 + hi) ^ sw) << 4);
            uint32_t a[4][4], b[2][4];
            #pragma unroll
            for (int mi = 0; mi < 4; mi++)
                ldmatrix_x4(a[mi][0], a[mi][1], a[mi][2], a[mi][3],
                            abase + (uint32_t)((wm * 64 + mi * 16 + l15) * 128) + uoff);
            #pragma unroll
            for (int nj = 0; nj < 2; nj++)
                ldmatrix_x4(b[nj][0], b[nj][1], b[nj][2], b[nj][3],
                            bbase + (uint32_t)((wn * 32 + nj * 16 + l15) * 128) + uoff);
            #pragma unroll
            for (int mi = 0; mi < 4; mi++)
                #pragma unroll
                for (int nj = 0; nj < 4; nj++)
                    mma_bf16(acc[mi][nj][0], acc[mi][nj][1], acc[mi][nj][2], acc[mi][nj][3],
                             a[mi][0], a[mi][1], a[mi][2], a[mi][3],
                             b[nj >> 1][nj & 1], b[nj >> 1][2 + (nj & 1)]);
        }
        __syncthreads();             // stage (c%3) free for reuse next iteration
    }

    // epilogue: per-row masked sum of exp(10*acc), 10*acc, count
    // labels read directly from global (each element touched exactly once)
    int q = lane >> 2, r4 = lane & 3;
    #pragma unroll
    for (int mi = 0; mi < 4; mi++) {
        #pragma unroll
        for (int h = 0; h < 2; h++) {
            int row = wm * 64 + mi * 16 + q + h * 8;
            const int* labrow = labels + (size_t)(m0 + row) * Cdim + n0;
            float se = 0.f, sx = 0.f, np = 0.f;
            #pragma unroll
            for (int nj = 0; nj < 4; nj++) {
                int col = wn * 32 + nj * 8 + 2 * r4;
                int2 lb = __ldg((const int2*)(labrow + col));
                float s0 = acc[mi][nj][2 * h + 0] * 10.f;
                float s1 = acc[mi][nj][2 * h + 1] * 10.f;
                if (lb.x > 0) { se += __expf(s0); sx += s0; np += 1.f; }
                if (lb.y > 0) { se += __expf(s1); sx += s1; np += 1.f; }
            }
            se += __shfl_xor_sync(0xFFFFFFFFu, se, 1);
            se += __shfl_xor_sync(0xFFFFFFFFu, se, 2);
            sx += __shfl_xor_sync(0xFFFFFFFFu, sx, 1);
            sx += __shfl_xor_sync(0xFFFFFFFFu, sx, 2);
            np += __shfl_xor_sync(0xFFFFFFFFu, np, 1);
            np += __shfl_xor_sync(0xFFFFFFFFu, np, 2);
            if (r4 == 0) {
                atomicAdd(&sE[row], se);
                atomicAdd(&sX[row], sx);
                atomicAdd(&sN[row], np);
            }
        }
    }
    __syncthreads();
    if (tid < 128) {
        int gr = attr * BROWS + m0 + tid;
        atomicAdd(&g_rowExp[gr], sE[tid]);
        atomicAdd(&g_rowSim[gr], sX[tid]);
        atomicAdd(&g_rowNp[gr],  sN[tid]);
    }
}

// parallel finalize: 64 blocks reduce per-row losses into g_acc[4]
__global__ void reduce_kernel() {
    __shared__ float sh[4][256];
    int t = threadIdx.x;
    int gstride = gridDim.x * blockDim.x;
    float v0 = 0.f, c0 = 0.f, v1 = 0.f, c1 = 0.f;
    for (int i = blockIdx.x * blockDim.x + t; i < BROWS; i += gstride) {
        float np = g_rowNp[i];
        if (np > 0.f) {
            float S = g_rowExp[i] + (1024.f - np);
            v0 += (np * logf(S) - g_rowSim[i]) / (np + 1e-8f);
            c0 += 1.f;
        }
        np = g_rowNp[BROWS + i];
        if (np > 0.f) {
            float S = g_rowExp[BROWS + i] + (512.f - np);
            v1 += (np * logf(S) - g_rowSim[BROWS + i]) / (np + 1e-8f);
            c1 += 1.f;
        }
    }
    sh[0][t] = v0; sh[1][t] = c0; sh[2][t] = v1; sh[3][t] = c1;
    __syncthreads();
    #pragma unroll
    for (int s = 128; s; s >>= 1) {
        if (t < s) {
            sh[0][t] += sh[0][t + s]; sh[1][t] += sh[1][t + s];
            sh[2][t] += sh[2][t + s]; sh[3][t] += sh[3][t + s];
        }
        __syncthreads();
    }
    if (t < 4) atomicAdd(&g_acc[t], sh[t][0]);
}

__global__ void scalar_kernel(float* out) {
    float sv0 = g_acc[0], sc0 = g_acc[1], sv1 = g_acc[2], sc1 = g_acc[3];
    float l1 = sv0 / fmaxf(sc0, 1.f);
    float l2 = sv1 / fmaxf(sc1, 1.f);
    float n1 = (sc0 > 0.f) ? 1.f : 0.f;
    float n2 = (sc1 > 0.f) ? 1.f : 0.f;
    float nv = n1 + n2;
    out[0] = (nv > 0.f) ? (l1 * n1 + l2 * n2) / fmaxf(nv, 1.f) : 0.f;
}

extern "C" void kernel_launch(void* const* d_in, const int* in_sizes, int n_in,
                              void* d_out, int out_size) {
    const float* img = (const float*)d_in[0];
    const float* pc  = (const float*)d_in[1];
    const float* ps  = (const float*)d_in[2];
    const int*   lc  = (const int*)d_in[3];
    const int*   lsh = (const int*)d_in[4];

    zero_kernel<<<(2 * BROWS + 255) / 256, 256>>>();
    norm_kernel<<<((BROWS + NPR) * 32 + 255) / 256, 256>>>(img, pc, ps);

    cudaFuncSetAttribute(gemm_kernel, cudaFuncAttributeMaxDynamicSharedMemorySize, SMEM_BYTES);
    gemm_kernel<<<dim3(12, 128), 256, SMEM_BYTES>>>(lc, lsh);

    reduce_kernel<<<64, 256>>>();
    scalar_kernel<<<1, 1>>>((float*)d_out);
}

// round 6
// speedup vs baseline: 2.3540x; 1.1289x over previous
#include <cuda_runtime.h>
#include <cuda_bf16.h>
#include <cstdint>

#define DI __device__ __forceinline__

static constexpr int BROWS = 16384;
static constexpr int DDIM  = 256;
static constexpr int C1    = 1024;
static constexpr int C2    = 512;
static constexpr int NPR   = C1 + C2;

// int8-quantized normalized rows (images, then color prompts, then shape prompts)
__device__ int8_t g_q[(BROWS + NPR) * DDIM];
__device__ float  g_inv[BROWS + NPR];     // amax/(127*||x||) per row
__device__ float  g_rowExp[2 * BROWS];
__device__ float  g_rowSim[2 * BROWS];
__device__ float  g_rowNp [2 * BROWS];
__device__ float  g_acc[4];               // v0, c0, v1, c1

// ---------------- helpers ----------------
DI uint32_t smem_u32(const void* p) {
    uint32_t a;
    asm("{ .reg .u64 t; cvta.to.shared.u64 t, %1; cvt.u32.u64 %0, t; }" : "=r"(a) : "l"(p));
    return a;
}
DI void cp16(uint32_t dst, const void* src) {
    asm volatile("cp.async.cg.shared.global [%0], [%1], 16;" :: "r"(dst), "l"(src));
}
DI void cp_commit() { asm volatile("cp.async.commit_group;"); }
template <int N> DI void cp_wait() {
    asm volatile("cp.async.wait_group %0;" :: "n"(N) : "memory");
}
DI void ldmatrix_x4(uint32_t& r0, uint32_t& r1, uint32_t& r2, uint32_t& r3, uint32_t addr) {
    asm volatile("ldmatrix.sync.aligned.m8n8.x4.shared.b16 {%0,%1,%2,%3}, [%4];"
                 : "=r"(r0), "=r"(r1), "=r"(r2), "=r"(r3) : "r"(addr));
}
// int8 MMA: m16n8k32, s32 accum. Fragment layout is byte-identical to f16 m16n8k16.
DI void mma_s8(int& d0, int& d1, int& d2, int& d3,
               uint32_t a0, uint32_t a1, uint32_t a2, uint32_t a3,
               uint32_t b0, uint32_t b1) {
    asm volatile("mma.sync.aligned.m16n8k32.row.col.s32.s8.s8.s32 "
                 "{%0,%1,%2,%3}, {%4,%5,%6,%7}, {%8,%9}, {%0,%1,%2,%3};"
                 : "+r"(d0), "+r"(d1), "+r"(d2), "+r"(d3)
                 : "r"(a0), "r"(a1), "r"(a2), "r"(a3), "r"(b0), "r"(b1));
}

// ---------------- SMEM layout ----------------
// [0,1536)   : per-row accumulators sE/sX/sN
// [2048,...) : A tile 128x256 int8 (32 KB), B tile 128x256 int8 (32 KB)
static constexpr int A_OFF = 2048;
static constexpr int B_OFF = A_OFF + 32768;
static constexpr int SMEM_BYTES = B_OFF + 32768;   // 67584 -> 2 CTAs/SM

// ---------------- kernels ----------------
__global__ void zero_kernel() {
    int i = blockIdx.x * blockDim.x + threadIdx.x;
    if (i < 2 * BROWS) { g_rowExp[i] = 0.f; g_rowSim[i] = 0.f; g_rowNp[i] = 0.f; }
    if (i < 4) g_acc[i] = 0.f;
}

// one warp per row: L2-normalize, per-row amax scale, quantize to int8
__global__ void norm_kernel(const float* __restrict__ img,
                            const float* __restrict__ pc,
                            const float* __restrict__ ps) {
    int warp = (blockIdx.x * blockDim.x + threadIdx.x) >> 5;
    int lane = threadIdx.x & 31;
    if (warp >= BROWS + NPR) return;
    const float* src;
    if (warp < BROWS)            src = img + (size_t)warp * DDIM;
    else if (warp < BROWS + C1)  src = pc  + (size_t)(warp - BROWS) * DDIM;
    else                         src = ps  + (size_t)(warp - BROWS - C1) * DDIM;

    float4 v0 = ((const float4*)src)[lane];
    float4 v1 = ((const float4*)src)[lane + 32];
    float ss = v0.x*v0.x + v0.y*v0.y + v0.z*v0.z + v0.w*v0.w
             + v1.x*v1.x + v1.y*v1.y + v1.z*v1.z + v1.w*v1.w;
    float am = fmaxf(fmaxf(fmaxf(fabsf(v0.x), fabsf(v0.y)), fmaxf(fabsf(v0.z), fabsf(v0.w))),
                     fmaxf(fmaxf(fabsf(v1.x), fabsf(v1.y)), fmaxf(fabsf(v1.z), fabsf(v1.w))));
    #pragma unroll
    for (int o = 16; o; o >>= 1) {
        ss += __shfl_xor_sync(0xFFFFFFFFu, ss, o);
        am = fmaxf(am, __shfl_xor_sync(0xFFFFFFFFu, am, o));
    }
    float rn = 1.f / fmaxf(sqrtf(ss), 1e-12f);
    float s  = (am > 0.f) ? (127.f / am) : 0.f;   // q = round(x * 127/amax)

    char4* dst = (char4*)(g_q + (size_t)warp * DDIM);
    dst[lane] = make_char4((char)__float2int_rn(v0.x * s), (char)__float2int_rn(v0.y * s),
                           (char)__float2int_rn(v0.z * s), (char)__float2int_rn(v0.w * s));
    dst[lane + 32] = make_char4((char)__float2int_rn(v1.x * s), (char)__float2int_rn(v1.y * s),
                                (char)__float2int_rn(v1.z * s), (char)__float2int_rn(v1.w * s));
    if (lane == 0) g_inv[warp] = am * rn * (1.f / 127.f);   // x_hat_i ~= q_i * g_inv
}

// fused 128x128xK256 int8 mma.sync GEMM + masked softmax-partial epilogue
__global__ void __launch_bounds__(256, 2)
gemm_kernel(const int* __restrict__ labels_color, const int* __restrict__ labels_shape) {
    extern __shared__ char smem_c[];
    uint32_t sb = smem_u32(smem_c);
    int tid = threadIdx.x, wid = tid >> 5, lane = tid & 31;

    int bx   = blockIdx.x;
    int attr = (bx >= 8) ? 1 : 0;
    int nt   = attr ? (bx - 8) : bx;
    int Cdim = attr ? C2 : C1;
    const int* labels = attr ? labels_shape : labels_color;
    int m0 = blockIdx.y * 128;
    int n0 = nt * 128;
    int prow0 = BROWS + (attr ? C1 : 0) + n0;
    const char* Ag = (const char*)(g_q + (size_t)m0 * DDIM);
    const char* Bg = (const char*)(g_q + (size_t)prow0 * DDIM);

    float* sE = (float*)smem_c;
    float* sX = sE + 128;
    float* sN = sE + 256;
    if (tid < 128) { sE[tid] = 0.f; sX[tid] = 0.f; sN[tid] = 0.f; }

    // whole-K tiles: A 128x256B, B 128x256B. 16 units of 16B per row,
    // swizzle within each 128B half: u' = (u&8) | ((u&7) ^ (row&7))
    #pragma unroll
    for (int j = 0; j < 8; j++) {
        int i = tid + j * 256;               // 2048 16B units per matrix
        int row = i >> 4, u = i & 15;
        uint32_t swo = (uint32_t)(row * 256 + (((u & 8) | ((u & 7) ^ (row & 7))) << 4));
        cp16(sb + A_OFF + swo, Ag + (size_t)row * 256 + u * 16);
        cp16(sb + B_OFF + swo, Bg + (size_t)row * 256 + u * 16);
    }
    cp_commit();

    // warp layout: 2 (M) x 4 (N); warp tile 64x32
    int wm = wid & 1, wn = wid >> 1;
    int acc[4][4][4];
    #pragma unroll
    for (int i = 0; i < 4; i++)
        #pragma unroll
        for (int j = 0; j < 4; j++)
            #pragma unroll
            for (int k = 0; k < 4; k++) acc[i][j][k] = 0;

    int l15 = lane & 15, sw = lane & 7, hi = lane >> 4;

    cp_wait<0>();
    __syncthreads();

    #pragma unroll
    for (int k = 0; k < 8; k++) {            // 8 k-steps of k32
        int u = k * 2 + hi;
        uint32_t uoff = (uint32_t)(((u & 8) | ((u & 7) ^ sw)) << 4);
        uint32_t a[4][4], b[2][4];
        #pragma unroll
        for (int mi = 0; mi < 4; mi++)
            ldmatrix_x4(a[mi][0], a[mi][1], a[mi][2], a[mi][3],
                        sb + A_OFF + (uint32_t)((wm * 64 + mi * 16 + l15) * 256) + uoff);
        #pragma unroll
        for (int nj = 0; nj < 2; nj++)
            ldmatrix_x4(b[nj][0], b[nj][1], b[nj][2], b[nj][3],
                        sb + B_OFF + (uint32_t)((wn * 32 + nj * 16 + l15) * 256) + uoff);
        #pragma unroll
        for (int mi = 0; mi < 4; mi++)
            #pragma unroll
            for (int nj = 0; nj < 4; nj++)
                mma_s8(acc[mi][nj][0], acc[mi][nj][1], acc[mi][nj][2], acc[mi][nj][3],
                       a[mi][0], a[mi][1], a[mi][2], a[mi][3],
                       b[nj >> 1][nj & 1], b[nj >> 1][2 + (nj & 1)]);
    }

    // epilogue: logit = acc * inva_row * (invb_col*10); masked exp/sim/count sums
    int q = lane >> 2, r4 = lane & 3;
    float invb10[4][2];
    #pragma unroll
    for (int nj = 0; nj < 4; nj++) {
        float2 ib = *(const float2*)(g_inv + prow0 + wn * 32 + nj * 8 + 2 * r4);
        invb10[nj][0] = ib.x * 10.f;
        invb10[nj][1] = ib.y * 10.f;
    }
    #pragma unroll
    for (int mi = 0; mi < 4; mi++) {
        #pragma unroll
        for (int h = 0; h < 2; h++) {
            int row = wm * 64 + mi * 16 + q + h * 8;
            float inva = g_inv[m0 + row];
            const int* labrow = labels + (size_t)(m0 + row) * Cdim + n0;
            float se = 0.f, sx = 0.f, np = 0.f;
            #pragma unroll
            for (int nj = 0; nj < 4; nj++) {
                int col = wn * 32 + nj * 8 + 2 * r4;
                int2 lb = __ldg((const int2*)(labrow + col));
                float s0 = (float)acc[mi][nj][2 * h + 0] * inva * invb10[nj][0];
                float s1 = (float)acc[mi][nj][2 * h + 1] * inva * invb10[nj][1];
                if (lb.x > 0) { se += __expf(s0); sx += s0; np += 1.f; }
                if (lb.y > 0) { se += __expf(s1); sx += s1; np += 1.f; }
            }
            se += __shfl_xor_sync(0xFFFFFFFFu, se, 1);
            se += __shfl_xor_sync(0xFFFFFFFFu, se, 2);
            sx += __shfl_xor_sync(0xFFFFFFFFu, sx, 1);
            sx += __shfl_xor_sync(0xFFFFFFFFu, sx, 2);
            np += __shfl_xor_sync(0xFFFFFFFFu, np, 1);
            np += __shfl_xor_sync(0xFFFFFFFFu, np, 2);
            if (r4 == 0) {
                atomicAdd(&sE[row], se);
                atomicAdd(&sX[row], sx);
                atomicAdd(&sN[row], np);
            }
        }
    }
    __syncthreads();
    if (tid < 128) {
        int gr = attr * BROWS + m0 + tid;
        atomicAdd(&g_rowExp[gr], sE[tid]);
        atomicAdd(&g_rowSim[gr], sX[tid]);
        atomicAdd(&g_rowNp[gr],  sN[tid]);
    }
}

// parallel finalize: 64 blocks reduce per-row losses into g_acc[4]
__global__ void reduce_kernel() {
    __shared__ float sh[4][256];
    int t = threadIdx.x;
    int gstride = gridDim.x * blockDim.x;
    float v0 = 0.f, c0 = 0.f, v1 = 0.f, c1 = 0.f;
    for (int i = blockIdx.x * blockDim.x + t; i < BROWS; i += gstride) {
        float np = g_rowNp[i];
        if (np > 0.f) {
            float S = g_rowExp[i] + (1024.f - np);
            v0 += (np * logf(S) - g_rowSim[i]) / (np + 1e-8f);
            c0 += 1.f;
        }
        np = g_rowNp[BROWS + i];
        if (np > 0.f) {
            float S = g_rowExp[BROWS + i] + (512.f - np);
            v1 += (np * logf(S) - g_rowSim[BROWS + i]) / (np + 1e-8f);
            c1 += 1.f;
        }
    }
    sh[0][t] = v0; sh[1][t] = c0; sh[2][t] = v1; sh[3][t] = c1;
    __syncthreads();
    #pragma unroll
    for (int s = 128; s; s >>= 1) {
        if (t < s) {
            sh[0][t] += sh[0][t + s]; sh[1][t] += sh[1][t + s];
            sh[2][t] += sh[2][t + s]; sh[3][t] += sh[3][t + s];
        }
        __syncthreads();
    }
    if (t < 4) atomicAdd(&g_acc[t], sh[t][0]);
}

__global__ void scalar_kernel(float* out) {
    float sv0 = g_acc[0], sc0 = g_acc[1], sv1 = g_acc[2], sc1 = g_acc[3];
    float l1 = sv0 / fmaxf(sc0, 1.f);
    float l2 = sv1 / fmaxf(sc1, 1.f);
    float n1 = (sc0 > 0.f) ? 1.f : 0.f;
    float n2 = (sc1 > 0.f) ? 1.f : 0.f;
    float nv = n1 + n2;
    out[0] = (nv > 0.f) ? (l1 * n1 + l2 * n2) / fmaxf(nv, 1.f) : 0.f;
}

extern "C" void kernel_launch(void* const* d_in, const int* in_sizes, int n_in,
                              void* d_out, int out_size) {
    const float* img = (const float*)d_in[0];
    const float* pc  = (const float*)d_in[1];
    const float* ps  = (const float*)d_in[2];
    const int*   lc  = (const int*)d_in[3];
    const int*   lsh = (const int*)d_in[4];

    zero_kernel<<<(2 * BROWS + 255) / 256, 256>>>();
    norm_kernel<<<((BROWS + NPR) * 32 + 255) / 256, 256>>>(img, pc, ps);

    cudaFuncSetAttribute(gemm_kernel, cudaFuncAttributeMaxDynamicSharedMemorySize, SMEM_BYTES);
    gemm_kernel<<<dim3(12, 128), 256, SMEM_BYTES>>>(lc, lsh);

    reduce_kernel<<<64, 256>>>();
    scalar_kernel<<<1, 1>>>((float*)d_out);
}

// round 7
// speedup vs baseline: 2.6456x; 1.1239x over previous
#include <cuda_runtime.h>
#include <cuda_bf16.h>
#include <cstdint>

#define DI __device__ __forceinline__

static constexpr int BROWS = 16384;
static constexpr int DDIM  = 256;
static constexpr int C1    = 1024;
static constexpr int C2    = 512;
static constexpr int NPR   = C1 + C2;

// int8-quantized normalized rows (images, then color prompts, then shape prompts)
__device__ int8_t g_q[(BROWS + NPR) * DDIM];
__device__ float  g_inv[BROWS + NPR];     // amax/(127*||x||) per row
__device__ float  g_rowExp[2 * BROWS];
__device__ float  g_rowSim[2 * BROWS];
__device__ float  g_rowNp [2 * BROWS];
__device__ float  g_acc[4];               // v0, c0, v1, c1

// ---------------- helpers ----------------
DI uint32_t smem_u32(const void* p) {
    uint32_t a;
    asm("{ .reg .u64 t; cvta.to.shared.u64 t, %1; cvt.u32.u64 %0, t; }" : "=r"(a) : "l"(p));
    return a;
}
DI void cp16(uint32_t dst, const void* src) {
    asm volatile("cp.async.cg.shared.global [%0], [%1], 16;" :: "r"(dst), "l"(src));
}
DI void cp_commit() { asm volatile("cp.async.commit_group;"); }
template <int N> DI void cp_wait() {
    asm volatile("cp.async.wait_group %0;" :: "n"(N) : "memory");
}
DI void ldmatrix_x4(uint32_t& r0, uint32_t& r1, uint32_t& r2, uint32_t& r3, uint32_t addr) {
    asm volatile("ldmatrix.sync.aligned.m8n8.x4.shared.b16 {%0,%1,%2,%3}, [%4];"
                 : "=r"(r0), "=r"(r1), "=r"(r2), "=r"(r3) : "r"(addr));
}
// int8 MMA: m16n8k32, s32 accum. Fragment layout is byte-identical to f16 m16n8k16.
DI void mma_s8(int& d0, int& d1, int& d2, int& d3,
               uint32_t a0, uint32_t a1, uint32_t a2, uint32_t a3,
               uint32_t b0, uint32_t b1) {
    asm volatile("mma.sync.aligned.m16n8k32.row.col.s32.s8.s8.s32 "
                 "{%0,%1,%2,%3}, {%4,%5,%6,%7}, {%8,%9}, {%0,%1,%2,%3};"
                 : "+r"(d0), "+r"(d1), "+r"(d2), "+r"(d3)
                 : "r"(a0), "r"(a1), "r"(a2), "r"(a3), "r"(b0), "r"(b1));
}

// ---------------- SMEM layout ----------------
// [0,1536)   : per-row accumulators sE/sX/sN
// [2048,...) : 2 pipeline stages, each A-chunk 128x128 int8 (16 KB) + B-chunk (16 KB)
static constexpr int STG_OFF   = 2048;
static constexpr int STG_BYTES = 32768;
static constexpr int SMEM_BYTES = STG_OFF + 2 * STG_BYTES;   // 67584 -> 2 CTAs/SM

// ---------------- kernels ----------------
// one warp per row: L2-normalize, per-row amax scale, quantize to int8.
// Also zeroes the accumulator arrays (merged zero_kernel).
__global__ void norm_kernel(const float* __restrict__ img,
                            const float* __restrict__ pc,
                            const float* __restrict__ ps) {
    int gidx = blockIdx.x * blockDim.x + threadIdx.x;
    if (gidx < 2 * BROWS) { g_rowExp[gidx] = 0.f; g_rowSim[gidx] = 0.f; g_rowNp[gidx] = 0.f; }
    if (gidx < 4) g_acc[gidx] = 0.f;

    int warp = gidx >> 5;
    int lane = threadIdx.x & 31;
    if (warp >= BROWS + NPR) return;
    const float* src;
    if (warp < BROWS)            src = img + (size_t)warp * DDIM;
    else if (warp < BROWS + C1)  src = pc  + (size_t)(warp - BROWS) * DDIM;
    else                         src = ps  + (size_t)(warp - BROWS - C1) * DDIM;

    float4 v0 = ((const float4*)src)[lane];
    float4 v1 = ((const float4*)src)[lane + 32];
    float ss = v0.x*v0.x + v0.y*v0.y + v0.z*v0.z + v0.w*v0.w
             + v1.x*v1.x + v1.y*v1.y + v1.z*v1.z + v1.w*v1.w;
    float am = fmaxf(fmaxf(fmaxf(fabsf(v0.x), fabsf(v0.y)), fmaxf(fabsf(v0.z), fabsf(v0.w))),
                     fmaxf(fmaxf(fabsf(v1.x), fabsf(v1.y)), fmaxf(fabsf(v1.z), fabsf(v1.w))));
    #pragma unroll
    for (int o = 16; o; o >>= 1) {
        ss += __shfl_xor_sync(0xFFFFFFFFu, ss, o);
        am = fmaxf(am, __shfl_xor_sync(0xFFFFFFFFu, am, o));
    }
    float rn = 1.f / fmaxf(sqrtf(ss), 1e-12f);
    float s  = (am > 0.f) ? (127.f / am) : 0.f;   // q = round(x * 127/amax)

    char4* dst = (char4*)(g_q + (size_t)warp * DDIM);
    dst[lane] = make_char4((char)__float2int_rn(v0.x * s), (char)__float2int_rn(v0.y * s),
                           (char)__float2int_rn(v0.z * s), (char)__float2int_rn(v0.w * s));
    dst[lane + 32] = make_char4((char)__float2int_rn(v1.x * s), (char)__float2int_rn(v1.y * s),
                                (char)__float2int_rn(v1.z * s), (char)__float2int_rn(v1.w * s));
    if (lane == 0) g_inv[warp] = am * rn * (1.f / 127.f);   // x_hat_i ~= q_i * g_inv
}

// load one K-chunk (A 128x128 int8 + B 128x128 int8) into a pipeline stage
// swizzled 128B rows, 16B-unit xor swizzle
DI void load_stage(uint32_t sbase, const char* Ag, const char* Bg, int c, int tid) {
    const char* ga = Ag + c * 128;    // chunk byte offset within 256B row
    const char* gb = Bg + c * 128;
    #pragma unroll
    for (int j = 0; j < 4; j++) {
        int i = tid + j * 256;        // 1024 16B units per matrix
        int row = i >> 3, u = i & 7;
        uint32_t dst = sbase + row * 128 + ((u ^ (row & 7)) << 4);
        cp16(dst,         ga + (size_t)row * 256 + u * 16);
        cp16(dst + 16384, gb + (size_t)row * 256 + u * 16);
    }
}

// fused 128x128xK256 int8 mma.sync GEMM + masked softmax-partial epilogue
__global__ void __launch_bounds__(256, 2)
gemm_kernel(const int* __restrict__ labels_color, const int* __restrict__ labels_shape) {
    extern __shared__ char smem_c[];
    uint32_t sb = smem_u32(smem_c);
    int tid = threadIdx.x, wid = tid >> 5, lane = tid & 31;

    int bx   = blockIdx.x;
    int attr = (bx >= 8) ? 1 : 0;
    int nt   = attr ? (bx - 8) : bx;
    int Cdim = attr ? C2 : C1;
    const int* labels = attr ? labels_shape : labels_color;
    int m0 = blockIdx.y * 128;
    int n0 = nt * 128;
    int prow0 = BROWS + (attr ? C1 : 0) + n0;
    const char* Ag = (const char*)(g_q + (size_t)m0 * DDIM);
    const char* Bg = (const char*)(g_q + (size_t)prow0 * DDIM);

    float* sE = (float*)smem_c;
    float* sX = sE + 128;
    float* sN = sE + 256;
    if (tid < 128) { sE[tid] = 0.f; sX[tid] = 0.f; sN[tid] = 0.f; }

    // pipeline prologue: both chunks in flight
    load_stage(sb + STG_OFF, Ag, Bg, 0, tid); cp_commit();
    load_stage(sb + STG_OFF + STG_BYTES, Ag, Bg, 1, tid); cp_commit();

    int wm = wid & 1, wn = wid >> 1;
    int q = lane >> 2, r4 = lane & 3;

    // prefetch this thread-quad's label lines into L2 (used in epilogue)
    if (r4 == 0) {
        #pragma unroll
        for (int mi = 0; mi < 4; mi++)
            #pragma unroll
            for (int h = 0; h < 2; h++) {
                int row = wm * 64 + mi * 16 + q + h * 8;
                const int* p = labels + (size_t)(m0 + row) * Cdim + n0 + wn * 32;
                asm volatile("prefetch.global.L2 [%0];" :: "l"(p));
            }
    }

    // warp layout: 2 (M) x 4 (N); warp tile 64x32
    int acc[4][4][4];
    #pragma unroll
    for (int i = 0; i < 4; i++)
        #pragma unroll
        for (int j = 0; j < 4; j++)
            #pragma unroll
            for (int k = 0; k < 4; k++) acc[i][j][k] = 0;

    int l15 = lane & 15, sw = lane & 7, hi = lane >> 4;

    #pragma unroll
    for (int c = 0; c < 2; c++) {
        if (c == 0) cp_wait<1>(); else cp_wait<0>();
        __syncthreads();
        uint32_t abase = sb + STG_OFF + c * STG_BYTES;
        uint32_t bbase = abase + 16384;
        #pragma unroll
        for (int k = 0; k < 4; k++) {        // 4 k-steps of k32 per chunk
            uint32_t uoff = (uint32_t)(((k * 2 + hi) ^ sw) << 4);
            uint32_t a[4][4], b[2][4];
            #pragma unroll
            for (int mi = 0; mi < 4; mi++)
                ldmatrix_x4(a[mi][0], a[mi][1], a[mi][2], a[mi][3],
                            abase + (uint32_t)((wm * 64 + mi * 16 + l15) * 128) + uoff);
            #pragma unroll
            for (int nj = 0; nj < 2; nj++)
                ldmatrix_x4(b[nj][0], b[nj][1], b[nj][2], b[nj][3],
                            bbase + (uint32_t)((wn * 32 + nj * 16 + l15) * 128) + uoff);
            #pragma unroll
            for (int mi = 0; mi < 4; mi++)
                #pragma unroll
                for (int nj = 0; nj < 4; nj++)
                    mma_s8(acc[mi][nj][0], acc[mi][nj][1], acc[mi][nj][2], acc[mi][nj][3],
                           a[mi][0], a[mi][1], a[mi][2], a[mi][3],
                           b[nj >> 1][nj & 1], b[nj >> 1][2 + (nj & 1)]);
        }
    }

    // epilogue: logit = acc * inva_row * (invb_col*10); masked exp/sim/count sums
    float invb10[4][2];
    #pragma unroll
    for (int nj = 0; nj < 4; nj++) {
        float2 ib = *(const float2*)(g_inv + prow0 + wn * 32 + nj * 8 + 2 * r4);
        invb10[nj][0] = ib.x * 10.f;
        invb10[nj][1] = ib.y * 10.f;
    }
    #pragma unroll
    for (int mi = 0; mi < 4; mi++) {
        #pragma unroll
        for (int h = 0; h < 2; h++) {
            int row = wm * 64 + mi * 16 + q + h * 8;
            float inva = g_inv[m0 + row];
            const int* labrow = labels + (size_t)(m0 + row) * Cdim + n0;
            float se = 0.f, sx = 0.f, np = 0.f;
            #pragma unroll
            for (int nj = 0; nj < 4; nj++) {
                int col = wn * 32 + nj * 8 + 2 * r4;
                int2 lb = __ldg((const int2*)(labrow + col));
                float s0 = (float)acc[mi][nj][2 * h + 0] * inva * invb10[nj][0];
                float s1 = (float)acc[mi][nj][2 * h + 1] * inva * invb10[nj][1];
                if (lb.x > 0) { se += __expf(s0); sx += s0; np += 1.f; }
                if (lb.y > 0) { se += __expf(s1); sx += s1; np += 1.f; }
            }
            se += __shfl_xor_sync(0xFFFFFFFFu, se, 1);
            se += __shfl_xor_sync(0xFFFFFFFFu, se, 2);
            sx += __shfl_xor_sync(0xFFFFFFFFu, sx, 1);
            sx += __shfl_xor_sync(0xFFFFFFFFu, sx, 2);
            np += __shfl_xor_sync(0xFFFFFFFFu, np, 1);
            np += __shfl_xor_sync(0xFFFFFFFFu, np, 2);
            if (r4 == 0) {
                atomicAdd(&sE[row], se);
                atomicAdd(&sX[row], sx);
                atomicAdd(&sN[row], np);
            }
        }
    }
    __syncthreads();
    if (tid < 128) {
        int gr = attr * BROWS + m0 + tid;
        atomicAdd(&g_rowExp[gr], sE[tid]);
        atomicAdd(&g_rowSim[gr], sX[tid]);
        atomicAdd(&g_rowNp[gr],  sN[tid]);
    }
}

// parallel finalize: 64 blocks reduce per-row losses into g_acc[4]
__global__ void reduce_kernel() {
    __shared__ float sh[4][256];
    int t = threadIdx.x;
    int gstride = gridDim.x * blockDim.x;
    float v0 = 0.f, c0 = 0.f, v1 = 0.f, c1 = 0.f;
    for (int i = blockIdx.x * blockDim.x + t; i < BROWS; i += gstride) {
        float np = g_rowNp[i];
        if (np > 0.f) {
            float S = g_rowExp[i] + (1024.f - np);
            v0 += (np * logf(S) - g_rowSim[i]) / (np + 1e-8f);
            c0 += 1.f;
        }
        np = g_rowNp[BROWS + i];
        if (np > 0.f) {
            float S = g_rowExp[BROWS + i] + (512.f - np);
            v1 += (np * logf(S) - g_rowSim[BROWS + i]) / (np + 1e-8f);
            c1 += 1.f;
        }
    }
    sh[0][t] = v0; sh[1][t] = c0; sh[2][t] = v1; sh[3][t] = c1;
    __syncthreads();
    #pragma unroll
    for (int s = 128; s; s >>= 1) {
        if (t < s) {
            sh[0][t] += sh[0][t + s]; sh[1][t] += sh[1][t + s];
            sh[2][t] += sh[2][t + s]; sh[3][t] += sh[3][t + s];
        }
        __syncthreads();
    }
    if (t < 4) atomicAdd(&g_acc[t], sh[t][0]);
}

__global__ void scalar_kernel(float* out) {
    float sv0 = g_acc[0], sc0 = g_acc[1], sv1 = g_acc[2], sc1 = g_acc[3];
    float l1 = sv0 / fmaxf(sc0, 1.f);
    float l2 = sv1 / fmaxf(sc1, 1.f);
    float n1 = (sc0 > 0.f) ? 1.f : 0.f;
    float n2 = (sc1 > 0.f) ? 1.f : 0.f;
    float nv = n1 + n2;
    out[0] = (nv > 0.f) ? (l1 * n1 + l2 * n2) / fmaxf(nv, 1.f) : 0.f;
}

extern "C" void kernel_launch(void* const* d_in, const int* in_sizes, int n_in,
                              void* d_out, int out_size) {
    const float* img = (const float*)d_in[0];
    const float* pc  = (const float*)d_in[1];
    const float* ps  = (const float*)d_in[2];
    const int*   lc  = (const int*)d_in[3];
    const int*   lsh = (const int*)d_in[4];

    norm_kernel<<<((BROWS + NPR) * 32 + 255) / 256, 256>>>(img, pc, ps);

    cudaFuncSetAttribute(gemm_kernel, cudaFuncAttributeMaxDynamicSharedMemorySize, SMEM_BYTES);
    gemm_kernel<<<dim3(12, 128), 256, SMEM_BYTES>>>(lc, lsh);

    reduce_kernel<<<64, 256>>>();
    scalar_kernel<<<1, 1>>>((float*)d_out);
}